// round 17
// baseline (speedup 1.0000x reference)
#include <cuda_runtime.h>
#include <cuda_bf16.h>
#include <stdint.h>

#define B_   8
#define C_   256
#define HW   4096
#define OC3  768
#define GRPS 96

// Scratch (alloc-free rule: __device__ globals)
__device__ float g_qkv[B_ * OC3 * HW];   // ~100.7 MB
__device__ float g_agg[B_ * OC3 * HW];   // ~100.7 MB
__device__ float g_kv [B_ * 64 * 72];    // per (b,head) 8x9 kv matrix

// Preconverted bf16 hi/lo weight buffers (weights only; x is split in-kernel)
__device__ __align__(16) __nv_bfloat16 g_wqhi[OC3 * C_];
__device__ __align__(16) __nv_bfloat16 g_wqlo[OC3 * C_];
__device__ __align__(16) __nv_bfloat16 g_wphi[C_ * 512];
__device__ __align__(16) __nv_bfloat16 g_wplo[C_ * 512];

// ===========================================================================
// helpers
// ===========================================================================
__device__ __forceinline__ uint32_t smem_u32(const void* p) {
    uint32_t a;
    asm("{ .reg .u64 t; cvta.to.shared.u64 t, %1; cvt.u32.u64 %0, t; }"
        : "=r"(a) : "l"(p));
    return a;
}
__device__ __forceinline__ void ldsm_x4(uint32_t& r0, uint32_t& r1,
                                        uint32_t& r2, uint32_t& r3, uint32_t addr) {
    asm volatile("ldmatrix.sync.aligned.m8n8.x4.shared.b16 {%0,%1,%2,%3}, [%4];"
        : "=r"(r0), "=r"(r1), "=r"(r2), "=r"(r3) : "r"(addr));
}
__device__ __forceinline__ void ldsm_x2t(uint32_t& r0, uint32_t& r1, uint32_t addr) {
    asm volatile("ldmatrix.sync.aligned.m8n8.x2.trans.shared.b16 {%0,%1}, [%2];"
        : "=r"(r0), "=r"(r1) : "r"(addr));
}
__device__ __forceinline__ void mma_bf16(float& c0, float& c1, float& c2, float& c3,
    uint32_t a0, uint32_t a1, uint32_t a2, uint32_t a3, uint32_t b0, uint32_t b1) {
    asm volatile("mma.sync.aligned.m16n8k16.row.col.f32.bf16.bf16.f32 "
        "{%0,%1,%2,%3}, {%4,%5,%6,%7}, {%8,%9}, {%0,%1,%2,%3};"
        : "+f"(c0), "+f"(c1), "+f"(c2), "+f"(c3)
        : "r"(a0), "r"(a1), "r"(a2), "r"(a3), "r"(b0), "r"(b1));
}
__device__ __forceinline__ void cpa16(uint32_t dst, const void* src) {
    asm volatile("cp.async.ca.shared.global [%0], [%1], 16;" :: "r"(dst), "l"(src));
}
#define CP_COMMIT() asm volatile("cp.async.commit_group;" ::: "memory")
#define CP_WAIT0()  asm volatile("cp.async.wait_group 0;" ::: "memory")

__device__ __forceinline__ void split4(float4 v, uint2& hi, uint2& lo) {
    __nv_bfloat162 h0 = __floats2bfloat162_rn(v.x, v.y);
    __nv_bfloat162 h1 = __floats2bfloat162_rn(v.z, v.w);
    float2 f0 = __bfloat1622float2(h0);
    float2 f1 = __bfloat1622float2(h1);
    __nv_bfloat162 l0 = __floats2bfloat162_rn(v.x - f0.x, v.y - f0.y);
    __nv_bfloat162 l1 = __floats2bfloat162_rn(v.z - f1.x, v.w - f1.y);
    hi = make_uint2(*(uint32_t*)&h0, *(uint32_t*)&h1);
    lo = make_uint2(*(uint32_t*)&l0, *(uint32_t*)&l1);
}

// ---------------------------------------------------------------------------
// K0: preconvert weights fp32 -> bf16 hi/lo (w_qkv + w_proj)
// ---------------------------------------------------------------------------
__global__ __launch_bounds__(256) void conv_w_k(const float* __restrict__ wq,
                                                const float* __restrict__ wp)
{
    int i4 = blockIdx.x * 256 + threadIdx.x;
    if (i4 < 49152) {                         // wqkv: 768*256/4
        float4 v = *(const float4*)(wq + (size_t)i4 * 4);
        uint2 hp, lp; split4(v, hp, lp);
        *(uint2*)(g_wqhi + (size_t)i4 * 4) = hp;
        *(uint2*)(g_wqlo + (size_t)i4 * 4) = lp;
    } else {                                  // wproj: 256*512/4
        int j = i4 - 49152;
        float4 v = *(const float4*)(wp + (size_t)j * 4);
        uint2 hp, lp; split4(v, hp, lp);
        *(uint2*)(g_wphi + (size_t)j * 4) = hp;
        *(uint2*)(g_wplo + (size_t)j * 4) = lp;
    }
}

// ---------------------------------------------------------------------------
// K1 (HMMA, x-resident): qkv[b,m,n] = sum_k w[m,k]*x[b,k,n]
// CTA = (128-token n-tile, batch). Prologue: load x fp32 once, split into
// K=256-resident smem B (hi/lo, ldmatrix [k][n] stride 272B). Then loop 6
// m-tiles with cp.async double-buffered W chunks (BK=64) + 3-pass HMMA.
// SMEM: Bhi 69632 | Blo 69632 | A 2x36864 = 212992 B. 512 thr, 4x4 warps.
// ---------------------------------------------------------------------------
#define K1_BLO  69632
#define K1_AOFF 139264
#define K1_AST  36864
#define K1_ALO  18432
#define K1_SMEM 212992

__global__ __launch_bounds__(512) void qkv_mma_k(const float* __restrict__ x)
{
    extern __shared__ char smc[];
    uint32_t sb = smem_u32(smc);
    int tid = threadIdx.x, lane = tid & 31, wrp = tid >> 5;
    int b = blockIdx.x & 7, n0 = (blockIdx.x >> 3) * 128;
    int wm = (wrp >> 2) * 32, wn = (wrp & 3) * 32;
    float* ob = g_qkv + (size_t)b * OC3 * HW;

    // ---- prologue: x[b, 0..255, n0..n0+127] fp32 -> resident B hi/lo ----
    {
        const float* xb = x + (size_t)b * C_ * HW + n0;
        int n4 = tid & 31, kb = tid >> 5;         // 16 k-rows per iter
        #pragma unroll 4
        for (int it = 0; it < 16; it++) {
            int k = it * 16 + kb;
            float4 v = *(const float4*)(xb + (size_t)k * HW + n4 * 4);
            uint2 hp, lp; split4(v, hp, lp);
            uint32_t dd = sb + (uint32_t)k * 272u + (uint32_t)n4 * 8u;
            *(uint2*)(smc + (dd - sb)) = hp;      // keep as smem stores
            *(uint2*)(smc + (dd - sb) + K1_BLO) = lp;
        }
    }

    // ---- W chunk staging (cp.async): chunk c = mt*4+kc ----
    auto stageA = [&](int c, int buf) {
        int mt = c >> 2, kc = c & 3;
        int m0 = mt * 128;
        uint32_t d = sb + K1_AOFF + buf * K1_AST;
        #pragma unroll
        for (int i = 0; i < 2; i++) {
            int cc = i * 512 + tid;               // 0..1023
            int row = cc >> 3, seg = cc & 7;
            size_t so = (size_t)(m0 + row) * C_ + kc * 64 + seg * 8;
            uint32_t dd = d + row * 144 + seg * 16;
            cpa16(dd, g_wqhi + so);
            cpa16(dd + K1_ALO, g_wqlo + so);
        }
    };

    stageA(0, 0); CP_COMMIT();
    float acc[2][4][4] = {};
    int buf = 0;

    for (int c = 0; c < 24; c++) {
        int kc = c & 3;
        CP_WAIT0();
        __syncthreads();
        if (c < 23) { stageA(c + 1, buf ^ 1); CP_COMMIT(); }

        uint32_t aBase = sb + K1_AOFF + buf * K1_AST;
        #pragma unroll
        for (int pass = 0; pass < 3; pass++) {
            uint32_t aB = aBase + ((pass == 2) ? K1_ALO : 0);
            uint32_t bB = sb + ((pass == 1) ? K1_BLO : 0);
            #pragma unroll
            for (int ks = 0; ks < 4; ks++) {
                uint32_t af[2][4], bf[4][2];
                #pragma unroll
                for (int mi = 0; mi < 2; mi++)
                    ldsm_x4(af[mi][0], af[mi][1], af[mi][2], af[mi][3],
                        aB + (uint32_t)((wm + mi * 16 + (lane & 15)) * 144
                                        + (ks * 16 + (lane >> 4) * 8) * 2));
                #pragma unroll
                for (int ni = 0; ni < 4; ni++)
                    ldsm_x2t(bf[ni][0], bf[ni][1],
                        bB + (uint32_t)((kc * 64 + ks * 16 + (lane & 15)) * 272
                                        + (wn + ni * 8) * 2));
                #pragma unroll
                for (int mi = 0; mi < 2; mi++)
                    #pragma unroll
                    for (int ni = 0; ni < 4; ni++)
                        mma_bf16(acc[mi][ni][0], acc[mi][ni][1],
                                 acc[mi][ni][2], acc[mi][ni][3],
                                 af[mi][0], af[mi][1], af[mi][2], af[mi][3],
                                 bf[ni][0], bf[ni][1]);
            }
        }
        if (kc == 3) {                            // m-tile complete: write out
            int m0 = (c >> 2) * 128;
            #pragma unroll
            for (int mi = 0; mi < 2; mi++) {
                int mr = m0 + wm + mi * 16 + (lane >> 2);
                #pragma unroll
                for (int ni = 0; ni < 4; ni++) {
                    int n = n0 + wn + ni * 8 + (lane & 3) * 2;
                    *(float2*)(ob + (size_t)mr * HW + n) =
                        make_float2(acc[mi][ni][0], acc[mi][ni][1]);
                    *(float2*)(ob + (size_t)(mr + 8) * HW + n) =
                        make_float2(acc[mi][ni][2], acc[mi][ni][3]);
                    acc[mi][ni][0] = acc[mi][ni][1] = 0.f;
                    acc[mi][ni][2] = acc[mi][ni][3] = 0.f;
                }
            }
        }
        buf ^= 1;
    }
}

// ---------------------------------------------------------------------------
// K2: fused depthwise 5x5 (pad 2) + grouped 8x8 pointwise. (unchanged)
// ---------------------------------------------------------------------------
__global__ __launch_bounds__(256, 3) void dw_agg_k(const float* __restrict__ wdw,
                                                   const float* __restrict__ wpw)
{
    int bg = blockIdx.z;
    int b = bg / GRPS, g = bg % GRPS;
    int y0 = blockIdx.y * 32, x0 = blockIdx.x * 32;

    __shared__ float s[8][36][36];
    __shared__ float swd[8][25];
    __shared__ float swp[64];
    int tid = threadIdx.x;

    if (tid < 200) swd[tid / 25][tid % 25] = wdw[(size_t)(g * 8 + tid / 25) * 25 + tid % 25];
    if (tid < 64)  swp[tid] = wpw[(size_t)g * 64 + tid];

    const float* src = g_qkv + ((size_t)b * OC3 + g * 8) * HW;
    for (int i = tid; i < 8 * 36 * 36; i += 256) {
        int ch = i / 1296, r = (i % 1296) / 36, c = i % 36;
        int y = y0 + r - 2, x = x0 + c - 2;
        float v = 0.f;
        if ((unsigned)y < 64u && (unsigned)x < 64u) v = src[(size_t)ch * HW + y * 64 + x];
        s[ch][r][c] = v;
    }
    __syncthreads();

    int px = tid & 31;
    int py0 = (tid >> 5) * 4;

    float acc[4][8] = {};
    for (int ch = 0; ch < 8; ch++) {
        float dwv[4] = {0.f, 0.f, 0.f, 0.f};
        #pragma unroll
        for (int dx = 0; dx < 5; dx++) {
            float col[8];
            #pragma unroll
            for (int r = 0; r < 8; r++) col[r] = s[ch][py0 + r][px + dx];
            #pragma unroll
            for (int dy = 0; dy < 5; dy++) {
                float wv = swd[ch][dy * 5 + dx];
                #pragma unroll
                for (int p = 0; p < 4; p++) dwv[p] = fmaf(col[p + dy], wv, dwv[p]);
            }
        }
        #pragma unroll
        for (int o = 0; o < 8; o++) {
            float wpv = swp[o * 8 + ch];
            #pragma unroll
            for (int p = 0; p < 4; p++) acc[p][o] = fmaf(dwv[p], wpv, acc[p][o]);
        }
    }

    float* dst = g_agg + ((size_t)b * OC3 + g * 8) * HW + (y0 + py0) * 64 + x0 + px;
    #pragma unroll
    for (int o = 0; o < 8; o++)
        #pragma unroll
        for (int p = 0; p < 4; p++)
            dst[(size_t)o * HW + p * 64] = acc[p][o];
}

// ---------------------------------------------------------------------------
// K3: kv reduction (unchanged)
// ---------------------------------------------------------------------------
__global__ __launch_bounds__(256) void kv_k()
{
    int bh = blockIdx.x;
    int b = bh >> 6, h = bh & 63;
    const float* base = (h < 32 ? g_qkv : g_agg) + ((size_t)b * OC3 + (h & 31) * 24) * HW;
    const float* kp = base + 8 * HW;
    const float* vp = base + 16 * HW;

    float acc[8][9] = {};
    for (int n = threadIdx.x; n < HW; n += 256) {
        float kr[8], vr[8];
        #pragma unroll
        for (int d = 0; d < 8; d++) {
            kr[d] = fmaxf(kp[(size_t)d * HW + n], 0.f);
            vr[d] = vp[(size_t)d * HW + n];
        }
        #pragma unroll
        for (int d = 0; d < 8; d++) {
            #pragma unroll
            for (int e = 0; e < 8; e++) acc[d][e] = fmaf(kr[d], vr[e], acc[d][e]);
            acc[d][8] += kr[d];
        }
    }
    __shared__ float sred[8][72];
    int w = threadIdx.x >> 5, lane = threadIdx.x & 31;
    #pragma unroll
    for (int d = 0; d < 8; d++)
        #pragma unroll
        for (int e = 0; e < 9; e++) {
            float v = acc[d][e];
            #pragma unroll
            for (int o = 16; o > 0; o >>= 1) v += __shfl_down_sync(0xffffffffu, v, o);
            if (lane == 0) sred[w][d * 9 + e] = v;
        }
    __syncthreads();
    if (threadIdx.x < 72) {
        float v = 0.f;
        #pragma unroll
        for (int w2 = 0; w2 < 8; w2++) v += sred[w2][threadIdx.x];
        g_kv[(size_t)bh * 72 + threadIdx.x] = v;
    }
}

// ---------------------------------------------------------------------------
// K4 (HMMA): fused attention + proj GEMM + BN + residual. (unchanged)
// ---------------------------------------------------------------------------
#define K4_WOFF  18432
#define K4_WST   36864
#define K4_AOFF  (18432 + 2 * K4_WST)          // 92160
#define K4_AST   34816
#define K4_ALO2  17408
#define K4_SMEM  (K4_AOFF + 2 * K4_AST)        // 161792

__global__ __launch_bounds__(512) void att_proj_mma_k(
    const float* __restrict__ x, const float* __restrict__ gamma,
    const float* __restrict__ beta, const float* __restrict__ mean,
    const float* __restrict__ var, float* __restrict__ out)
{
    extern __shared__ char smc[];
    float* kv_s = (float*)smc;
    uint32_t sb = smem_u32(smc);

    int tid = threadIdx.x, lane = tid & 31, wrp = tid >> 5;
    int b = blockIdx.z, n0 = blockIdx.x * 128, m0 = blockIdx.y * 128;
    int wm = (wrp >> 2) * 32, wn = (wrp & 3) * 32;
    int nl = tid & 127, hslot = tid >> 7;     // 0..3

    for (int i = tid; i < 4608; i += 512) kv_s[i] = g_kv[(size_t)b * 4608 + i];

    float acc[2][4][4] = {};

    auto stageW = [&](int hc, int s) {
        uint32_t d = sb + K4_WOFF + s * K4_WST;
        #pragma unroll
        for (int i = 0; i < 2; i++) {
            int c = i * 512 + tid;
            int row = c >> 3, seg = c & 7;
            size_t so = (size_t)(m0 + row) * 512 + hc * 64 + seg * 8;
            uint32_t dd = d + row * 144 + seg * 16;
            cpa16(dd, g_wphi + so);
            cpa16(dd + 18432, g_wplo + so);
        }
    };

    float qr[2][8];
    auto preloadQ = [&](int hc) {
        #pragma unroll
        for (int i = 0; i < 2; i++) {
            int h = hc * 8 + hslot + i * 4;
            const float* src = (h < 32 ? g_qkv : g_agg)
                             + ((size_t)b * OC3 + (h & 31) * 24) * HW + n0 + nl;
            #pragma unroll
            for (int d = 0; d < 8; d++) qr[i][d] = fmaxf(src[(size_t)d * HW], 0.f);
        }
    };

    stageW(0, 0); CP_COMMIT();
    preloadQ(0);
    __syncthreads();          // kv_s ready

    for (int hc = 0; hc < 8; hc++) {
        CP_WAIT0();
        __syncthreads();      // W(hc) visible; all MMA(hc-1) done
        if (hc < 7) { stageW(hc + 1, (hc + 1) & 1); CP_COMMIT(); }

        __nv_bfloat16* aHiP = (__nv_bfloat16*)(smc + K4_AOFF + (hc & 1) * K4_AST);
        __nv_bfloat16* aLoP = aHiP + 8704;      // +17408 B
        #pragma unroll
        for (int i = 0; i < 2; i++) {
            int hl = hslot + i * 4;
            int h = hc * 8 + hl;
            const float* kvh = kv_s + h * 72;
            float den = 0.f;
            #pragma unroll
            for (int d = 0; d < 8; d++) den = fmaf(qr[i][d], kvh[d * 9 + 8], den);
            float inv = 1.f / (den + 1e-15f);
            #pragma unroll
            for (int e = 0; e < 8; e++) {
                float s = 0.f;
                #pragma unroll
                for (int d = 0; d < 8; d++) s = fmaf(qr[i][d], kvh[d * 9 + e], s);
                s *= inv;
                __nv_bfloat16 hbv = __float2bfloat16(s);
                __nv_bfloat16 lbv = __float2bfloat16(s - __bfloat162float(hbv));
                int row = hl * 8 + e;
                aHiP[row * 136 + nl] = hbv;
                aLoP[row * 136 + nl] = lbv;
            }
        }
        if (hc < 7) preloadQ(hc + 1);           // global loads behind MMA
        __syncthreads();                        // att ready

        uint32_t wBase = sb + K4_WOFF + (hc & 1) * K4_WST;
        uint32_t bBase = sb + K4_AOFF + (hc & 1) * K4_AST;
        #pragma unroll
        for (int pass = 0; pass < 3; pass++) {
            uint32_t aB = wBase + ((pass == 2) ? 18432 : 0);
            uint32_t bB = bBase + ((pass == 1) ? K4_ALO2 : 0);
            #pragma unroll
            for (int ks = 0; ks < 4; ks++) {
                uint32_t af[2][4], bf[4][2];
                #pragma unroll
                for (int mi = 0; mi < 2; mi++)
                    ldsm_x4(af[mi][0], af[mi][1], af[mi][2], af[mi][3],
                        aB + (uint32_t)((wm + mi * 16 + (lane & 15)) * 144
                                        + (ks * 16 + (lane >> 4) * 8) * 2));
                #pragma unroll
                for (int ni = 0; ni < 4; ni++)
                    ldsm_x2t(bf[ni][0], bf[ni][1],
                        bB + (uint32_t)((ks * 16 + (lane & 15)) * 272
                                        + (wn + ni * 8) * 2));
                #pragma unroll
                for (int mi = 0; mi < 2; mi++)
                    #pragma unroll
                    for (int ni = 0; ni < 4; ni++)
                        mma_bf16(acc[mi][ni][0], acc[mi][ni][1],
                                 acc[mi][ni][2], acc[mi][ni][3],
                                 af[mi][0], af[mi][1], af[mi][2], af[mi][3],
                                 bf[ni][0], bf[ni][1]);
            }
        }
    }

    #pragma unroll
    for (int mi = 0; mi < 2; mi++) {
        #pragma unroll
        for (int half = 0; half < 2; half++) {
            int o = m0 + wm + mi * 16 + (lane >> 2) + half * 8;
            float invg = gamma[o] / sqrtf(var[o] + 1e-6f);
            float bias = beta[o] - mean[o] * invg;
            #pragma unroll
            for (int ni = 0; ni < 4; ni++) {
                int n = n0 + wn + ni * 8 + (lane & 3) * 2;
                size_t off = ((size_t)b * C_ + o) * HW + n;
                float2 xv = *(const float2*)(x + off);
                float2 r;
                r.x = xv.x + acc[mi][ni][half * 2 + 0] * invg + bias;
                r.y = xv.y + acc[mi][ni][half * 2 + 1] * invg + bias;
                *(float2*)(out + off) = r;
            }
        }
    }
}

// ---------------------------------------------------------------------------
extern "C" void kernel_launch(void* const* d_in, const int* in_sizes, int n_in,
                              void* d_out, int out_size)
{
    const float* x     = (const float*)d_in[0];
    const float* wqkv  = (const float*)d_in[1];
    const float* wdw   = (const float*)d_in[2];
    const float* wpw   = (const float*)d_in[3];
    const float* wproj = (const float*)d_in[4];
    const float* gamma = (const float*)d_in[5];
    const float* beta  = (const float*)d_in[6];
    const float* mean  = (const float*)d_in[7];
    const float* var   = (const float*)d_in[8];
    float* out = (float*)d_out;

    conv_w_k<<<320, 256>>>(wqkv, wproj);

    cudaFuncSetAttribute(qkv_mma_k, cudaFuncAttributeMaxDynamicSharedMemorySize, K1_SMEM);
    qkv_mma_k<<<256, 512, K1_SMEM>>>(x);

    dw_agg_k<<<dim3(2, 2, B_ * GRPS), 256>>>(wdw, wpw);
    kv_k<<<B_ * 64, 256>>>();

    cudaFuncSetAttribute(att_proj_mma_k, cudaFuncAttributeMaxDynamicSharedMemorySize, K4_SMEM);
    att_proj_mma_k<<<dim3(32, 2, B_), 512, K4_SMEM>>>(x, gamma, beta, mean, var, out);
}